// round 3
// baseline (speedup 1.0000x reference)
#include <cuda_runtime.h>
#include <cstdint>

#define H 128
#define W 128
#define NS 8
#define TY 16
#define SROWS (TY + 8)   // 24
#define SCOLS 140        // 128 + 8 halo + pad (even => float2-aligned rows)

__device__ __forceinline__ float2 ffma2(float2 a, float2 b, float2 c) {
    float2 d;
    asm("fma.rn.f32x2 %0, %1, %2, %3;"
        : "=l"(reinterpret_cast<uint64_t&>(d))
        : "l"(reinterpret_cast<uint64_t&>(a)),
          "l"(reinterpret_cast<uint64_t&>(b)),
          "l"(reinterpret_cast<uint64_t&>(c)));
    return d;
}

// 4 output rows x 2 cols for one (s, x-subtile).
// sb: &s_in[rowbase][aligned_col]. PAR: true col == aligned_col + PAR.
template<int PAR>
__device__ __forceinline__ void conv4(const float* __restrict__ sb,
                                      const float2* __restrict__ fp,
                                      float* __restrict__ op)
{
    float2 acc[4];
    #pragma unroll
    for (int y = 0; y < 4; ++y) acc[y] = make_float2(0.f, 0.f);

    #pragma unroll
    for (int k = 0; k < 8; ++k) {
        const float* r = sb + k * SCOLS;
        float2 q0 = *(const float2*)(r + 0);
        float2 q1 = *(const float2*)(r + 2);
        float2 q2 = *(const float2*)(r + 4);
        float2 p0, p1, p2, p3, p4;
        if (PAR == 0) {
            p0 = q0;
            p1 = make_float2(q0.y, q1.x);
            p2 = q1;
            p3 = make_float2(q1.y, q2.x);
            p4 = q2;
        } else {
            float2 q3 = *(const float2*)(r + 6);
            p0 = make_float2(q0.y, q1.x);
            p1 = q1;
            p2 = make_float2(q1.y, q2.x);
            p3 = q2;
            p4 = make_float2(q2.y, q3.x);
        }
        #pragma unroll
        for (int y = 0; y < 4; ++y) {
            const int i = k - y;            // compile-time after unroll
            if (i >= 0 && i < 5) {
                acc[y] = ffma2(fp[i * 5 + 0], p0, acc[y]);
                acc[y] = ffma2(fp[i * 5 + 1], p1, acc[y]);
                acc[y] = ffma2(fp[i * 5 + 2], p2, acc[y]);
                acc[y] = ffma2(fp[i * 5 + 3], p3, acc[y]);
                acc[y] = ffma2(fp[i * 5 + 4], p4, acc[y]);
            }
        }
    }
    #pragma unroll
    for (int y = 0; y < 4; ++y)
        *(float2*)(op + y * W) = acc[y];    // STG.64, 8B aligned
}

__global__ void __launch_bounds__(128, 6)
shifted_conv_kernel(const float* __restrict__ tens,
                    const float* __restrict__ filters,
                    const int* __restrict__ shifts,
                    float* __restrict__ out)
{
    __shared__ float  s_in[SROWS][SCOLS];
    __shared__ float2 s_fp[NS * 25];   // splatted filter pairs
    __shared__ int    s_sh[NS * 2];

    const int n    = blockIdx.x;        // 0..255 (B*C)
    const int y0   = blockIdx.y * TY;   // 0..112 step 16
    const int tid  = threadIdx.x;
    const int lane = tid & 31;
    const int wrp  = tid >> 5;

    for (int i = tid; i < NS * 25; i += 128) {
        float f = filters[i];
        s_fp[i] = make_float2(f, f);
    }
    if (tid < NS * 2) s_sh[tid] = shifts[tid];

    const float* inp = tens + (size_t)n * (H * W);
    for (int idx = tid; idx < SROWS * SCOLS; idx += 128) {
        int r  = idx / SCOLS;
        int c  = idx - r * SCOLS;
        int gy = y0 - 4 + r;
        int gx = c - 4;
        float v = 0.0f;
        if (gy >= 0 && gy < H && gx >= 0 && gx < W)
            v = inp[gy * W + gx];
        s_in[r][c] = v;
    }
    __syncthreads();

    const int ybase = wrp * 4;          // 4 output rows per warp
    float* outw = out + (size_t)n * (NS * H * W) + (size_t)(y0 + ybase) * W;

    #pragma unroll 1
    for (int s = 0; s < NS; ++s) {
        const int sy = s_sh[2 * s + 0];
        const int sx = s_sh[2 * s + 1];

        float2 fp[25];
        #pragma unroll
        for (int t = 0; t < 25; ++t) fp[t] = s_fp[s * 25 + t];

        const int rowbase = ybase + 4 - sy;     // [0, 16]
        const int col0    = 2 * lane + 4 - sx;  // parity == parity of sx
        float* ops = outw + (size_t)s * (H * W) + 2 * lane;

        if (!(sx & 1)) {
            const float* sb = &s_in[rowbase][col0];
            conv4<0>(sb,      fp, ops);
            conv4<0>(sb + 64, fp, ops + 64);
        } else {
            const float* sb = &s_in[rowbase][col0 - 1];
            conv4<1>(sb,      fp, ops);
            conv4<1>(sb + 64, fp, ops + 64);
        }
    }
}

extern "C" void kernel_launch(void* const* d_in, const int* in_sizes, int n_in,
                              void* d_out, int out_size)
{
    const float* tens    = (const float*)d_in[0];
    const float* filters = (const float*)d_in[1];
    const int*   shifts  = (const int*)d_in[2];
    float*       out     = (float*)d_out;

    dim3 grid(256, H / TY);   // (B*C, y-tiles) = 2048 blocks
    shifted_conv_kernel<<<grid, 128>>>(tens, filters, shifts, out);
}